// round 2
// baseline (speedup 1.0000x reference)
#include <cuda_runtime.h>
#include <math.h>
#include <stdint.h>

// ---------------------------------------------------------------------------
// Problem constants
// ---------------------------------------------------------------------------
#define N_R      2000
#define N_P      1512
#define M_TOT    3512            // N_R + N_P
#define K_ATT    3000
#define N_ATT1   2048
#define K_FUN    5603
#define N_FUN1   4096
#define N_E      256             // output cols of each second MLP GEMM
#define D_E      512             // concat width
#define BATCH    8192
#define PROTEIN  1512

// d_out layout (floats): e_r | e_p | output | flat
#define OUT_OFF  (M_TOT * D_E)           // 1,798,144
#define FLAT_OFF (OUT_OFF + BATCH * 2)   // 1,814,528

// scratch hidden buffer (shared by att and fun stages, sequential use)
__device__ float g_hid[(size_t)M_TOT * N_FUN1];   // 3512*4096 floats

// ---------------------------------------------------------------------------
// Tiled SGEMM with fused epilogue.
//   C[gr*ldc + cOff + gc] = act( sum_k A[gr][k]*B[k][gc] + bias[gc] )
// A is a virtual concat of A0 (M0 rows) and A1 (M-M0 rows), row-major, K cols.
// EPI: 0 = exact GELU, 1 = sigmoid
// ---------------------------------------------------------------------------
template<int BM, int BN, int TM, int TN, int EPI>
__global__ void __launch_bounds__(256)
sgemm_k(const float* __restrict__ A0, const float* __restrict__ A1, int M0,
        const float* __restrict__ Bm, const float* __restrict__ bias,
        float* __restrict__ C, int M, int N, int K, int ldc, int cOff)
{
    constexpr int BK = 8;
    constexpr int TX = BN / TN;         // threads along N
    constexpr int TY = BM / TM;         // threads along M
    static_assert(TX * TY == 256, "256 threads");
    constexpr int LA = BM * BK / 256;   // A elems per thread per tile
    constexpr int LB = BN * BK / 256;

    __shared__ float As[BK][BM];
    __shared__ float Bs[BK][BN];

    const int tid = threadIdx.x;
    const int tx = tid % TX;
    const int ty = tid / TX;
    const int bx = blockIdx.x;
    const int by = blockIdx.y;

    float acc[TM][TN];
#pragma unroll
    for (int i = 0; i < TM; i++)
#pragma unroll
        for (int j = 0; j < TN; j++) acc[i][j] = 0.f;

    const int ktiles = (K + BK - 1) / BK;
    for (int kt = 0; kt < ktiles; kt++) {
        const int k0 = kt * BK;
        // load A tile (guarded; rows from A0/A1 virtual concat)
#pragma unroll
        for (int l = 0; l < LA; l++) {
            int e = tid * LA + l;
            int r = e >> 3, k = e & 7;
            int gr = by * BM + r;
            int gk = k0 + k;
            float v = 0.f;
            if (gr < M && gk < K) {
                v = (gr < M0) ? A0[(size_t)gr * K + gk]
                              : A1[(size_t)(gr - M0) * K + gk];
            }
            As[k][r] = v;
        }
        // load B tile (N assumed multiple of BN)
#pragma unroll
        for (int l = 0; l < LB; l++) {
            int e = tid * LB + l;
            int k = e / BN, n = e % BN;
            int gk = k0 + k;
            int gn = bx * BN + n;
            Bs[k][n] = (gk < K) ? Bm[(size_t)gk * N + gn] : 0.f;
        }
        __syncthreads();

#pragma unroll
        for (int k = 0; k < BK; k++) {
            float a[TM], b[TN];
            const float4* ap = reinterpret_cast<const float4*>(&As[k][ty * TM]);
#pragma unroll
            for (int v = 0; v < TM / 4; v++) {
                float4 t = ap[v];
                a[4*v+0]=t.x; a[4*v+1]=t.y; a[4*v+2]=t.z; a[4*v+3]=t.w;
            }
            const float4* bp = reinterpret_cast<const float4*>(&Bs[k][tx * TN]);
#pragma unroll
            for (int v = 0; v < TN / 4; v++) {
                float4 t = bp[v];
                b[4*v+0]=t.x; b[4*v+1]=t.y; b[4*v+2]=t.z; b[4*v+3]=t.w;
            }
#pragma unroll
            for (int i = 0; i < TM; i++)
#pragma unroll
                for (int j = 0; j < TN; j++)
                    acc[i][j] = fmaf(a[i], b[j], acc[i][j]);
        }
        __syncthreads();
    }

    // epilogue
#pragma unroll
    for (int i = 0; i < TM; i++) {
        int gr = by * BM + ty * TM + i;
        if (gr >= M) continue;
#pragma unroll
        for (int j = 0; j < TN; j++) {
            int gc = bx * BN + tx * TN + j;
            float v = acc[i][j] + bias[gc];
            if (EPI == 0) {
                // exact GELU: x * 0.5 * (1 + erf(x/sqrt(2)))
                v = 0.5f * v * (1.0f + erff(v * 0.70710678118654752440f));
            } else {
                v = 1.0f / (1.0f + expf(-v));
            }
            C[(size_t)gr * ldc + cOff + gc] = v;
        }
    }
}

// ---------------------------------------------------------------------------
// Fused per-sample conv pipeline:
//   gather e_r/e_p rows -> conv1(3x5,pad2)+leaky+avgpool2 -> sh1 (16x2x256)
//   -> conv2(3x5,pad2)+leaky+maxpool2+tanh -> flat (8192) -> flat@W_out
// One CTA (256 threads) per sample. Dynamic smem.
// ---------------------------------------------------------------------------
// smem float offsets
#define OFF_SX    0                     // 2*516
#define OFF_SH1   1032                  // 16*2*260 = 8320
#define OFF_SW1   (OFF_SH1 + 8320)      // 240
#define OFF_SB1   (OFF_SW1 + 240)       // 16
#define OFF_SW2T  (OFF_SB1 + 16)        // 7680  (transposed: [kh*5+kw][ci][c])
#define OFF_SB2   (OFF_SW2T + 7680)     // 32
#define OFF_SFLAT (OFF_SB2 + 32)        // 128*65 = 8320
#define OFF_SRED  (OFF_SFLAT + 8320)    // 16
#define CONV_SMEM_FLOATS (OFF_SRED + 16)
#define CONV_SMEM_BYTES  (CONV_SMEM_FLOATS * 4)

__device__ __forceinline__ float leaky_f(float x) {
    return fmaxf(x, 0.01f * x);
}

__global__ void __launch_bounds__(256)
conv_fused_kernel(const float* __restrict__ e,        // d_out (e region)
                  const int*   __restrict__ idx,
                  const float* __restrict__ w1,       // 16*1*3*5
                  const float* __restrict__ b1,       // 16
                  const float* __restrict__ w2,       // 32*16*3*5
                  const float* __restrict__ b2,       // 32
                  const float* __restrict__ Wout,     // 8192*2
                  const float* __restrict__ bout,     // 2
                  float* __restrict__ out)            // d_out base
{
    extern __shared__ float sm[];
    float* sx    = sm + OFF_SX;
    float* sh1   = sm + OFF_SH1;
    float* sw1   = sm + OFF_SW1;
    float* sb1   = sm + OFF_SB1;
    float* sw2t  = sm + OFF_SW2T;
    float* sb2   = sm + OFF_SB2;
    float* sflat = sm + OFF_SFLAT;
    float* sred  = sm + OFF_SRED;

    const int tid = threadIdx.x;
    const int b   = blockIdx.x;

    // --- gather input rows ---
    const int id0  = idx[b];
    const int r_no = id0 / PROTEIN;
    const int p_no = id0 % PROTEIN;
    const float* er = e + (size_t)r_no * D_E;
    const float* ep = e + (size_t)(N_R + p_no) * D_E;
    for (int i = tid; i < D_E; i += 256) {
        sx[2 + i]       = er[i];
        sx[516 + 2 + i] = ep[i];
    }
    if (tid < 2) {
        float* row = sx + tid * 516;
        row[0] = 0.f; row[1] = 0.f; row[514] = 0.f; row[515] = 0.f;
    }
    // --- weights to smem ---
    for (int i = tid; i < 240; i += 256) sw1[i] = w1[i];
    if (tid < 16) sb1[tid] = b1[tid];
    for (int i = tid; i < 7680; i += 256) {
        int c  = i / 240;
        int ci = (i % 240) / 15;
        int kh = (i % 15) / 5;
        int kw = i % 5;
        sw2t[((kh * 5 + kw) * 16 + ci) * 32 + c] = w2[i];
    }
    if (tid < 32) sb2[tid] = b2[tid];
    __syncthreads();

    // --- conv1 + leaky + avgpool -> sh1[co][hh][2+pw], padded stride 260 ---
    // For pool row hh: "double" output = P.row1 + Q.row(2-2hh);
    //                  "single" output = P.row(2-2hh);  P = input row hh.
    for (int j = 0; j < 32; j++) {
        const int co = j >> 1;
        const int hh = j & 1;
        const int pw = tid;
        const float* P = sx + hh * 516 + 2 * pw;
        const float* Q = sx + (1 - hh) * 516 + 2 * pw;
        const float* wrow = sw1 + co * 15;
        const int qrow = 2 - 2 * hh;
        float wD[5], wQ[5];
#pragma unroll
        for (int t = 0; t < 5; t++) { wD[t] = wrow[5 + t]; wQ[t] = wrow[qrow * 5 + t]; }
        float p[6], q[6];
#pragma unroll
        for (int t = 0; t < 6; t++) { p[t] = P[t]; q[t] = Q[t]; }
        const float bz = sb1[co];
        float d0 = bz, d1 = bz, s0 = bz, s1 = bz;
#pragma unroll
        for (int kw = 0; kw < 5; kw++) {
            d0 = fmaf(p[kw],   wD[kw], d0); d0 = fmaf(q[kw],   wQ[kw], d0);
            d1 = fmaf(p[kw+1], wD[kw], d1); d1 = fmaf(q[kw+1], wQ[kw], d1);
            s0 = fmaf(p[kw],   wQ[kw], s0);
            s1 = fmaf(p[kw+1], wQ[kw], s1);
        }
        float v = 0.25f * (leaky_f(d0) + leaky_f(d1) + leaky_f(s0) + leaky_f(s1));
        sh1[(co * 2 + hh) * 260 + 2 + pw] = v;
    }
    if (tid < 32) {
        float* row = sh1 + tid * 260;
        row[0] = 0.f; row[1] = 0.f; row[258] = 0.f; row[259] = 0.f;
    }
    __syncthreads();

    // --- conv2 + leaky + maxpool + tanh -> sflat ---
    // thread = (c = lane, hh, pwb); all smem loads broadcast or stride-1.
    {
        const int c   = tid & 31;
        const int hh  = (tid >> 5) & 1;
        const int pwb = tid >> 6;
        const float bz2 = sb2[c];
        const int qk = 2 - 2 * hh;

        for (int g = 0; g < 8; g++) {
            const int pw0 = pwb * 32 + g * 4;
            float aD0[4], aD1[4], aS0[4], aS1[4];
#pragma unroll
            for (int p2 = 0; p2 < 4; p2++) { aD0[p2]=bz2; aD1[p2]=bz2; aS0[p2]=bz2; aS1[p2]=bz2; }

            for (int ci = 0; ci < 16; ci++) {
                const float* rowP = sh1 + (ci * 2 + hh) * 260 + 2 * pw0;
                const float* rowQ = sh1 + (ci * 2 + (1 - hh)) * 260 + 2 * pw0;
                float P[12], Q[12];
#pragma unroll
                for (int t = 0; t < 12; t++) { P[t] = rowP[t]; Q[t] = rowQ[t]; }
                float wD[5], wQ[5];
#pragma unroll
                for (int t = 0; t < 5; t++) {
                    wD[t] = sw2t[((5 + t) * 16 + ci) * 32 + c];
                    wQ[t] = sw2t[((qk * 5 + t) * 16 + ci) * 32 + c];
                }
#pragma unroll
                for (int p2 = 0; p2 < 4; p2++) {
#pragma unroll
                    for (int kw = 0; kw < 5; kw++) {
                        const float pv  = P[2*p2 + kw];
                        const float pv1 = P[2*p2 + 1 + kw];
                        const float qv  = Q[2*p2 + kw];
                        const float qv1 = Q[2*p2 + 1 + kw];
                        aD0[p2] = fmaf(pv,  wD[kw], aD0[p2]);
                        aD0[p2] = fmaf(qv,  wQ[kw], aD0[p2]);
                        aD1[p2] = fmaf(pv1, wD[kw], aD1[p2]);
                        aD1[p2] = fmaf(qv1, wQ[kw], aD1[p2]);
                        aS0[p2] = fmaf(pv,  wQ[kw], aS0[p2]);
                        aS1[p2] = fmaf(pv1, wQ[kw], aS1[p2]);
                    }
                }
            }
#pragma unroll
            for (int p2 = 0; p2 < 4; p2++) {
                float m = fmaxf(fmaxf(aD0[p2], aD1[p2]), fmaxf(aS0[p2], aS1[p2]));
                float v = tanhf(leaky_f(m));
                sflat[(pw0 + p2) * 65 + hh * 32 + c] = v;   // stride-65 pad: conflict-free
            }
        }
    }
    __syncthreads();

    // --- write flat (coalesced) and fused flat @ W_out ---
    float p0 = 0.f, p1 = 0.f;
    float* flatOut = out + FLAT_OFF + (size_t)b * 8192;
    for (int j = 0; j < 32; j++) {
        const int o  = j * 256 + tid;
        const int pw = o & 127;
        const int hh = (o >> 7) & 1;
        const int c  = o >> 8;
        const float v = sflat[pw * 65 + hh * 32 + c];
        flatOut[o] = v;
        p0 = fmaf(v, Wout[2 * o],     p0);
        p1 = fmaf(v, Wout[2 * o + 1], p1);
    }
    // block reduce 2 sums
#pragma unroll
    for (int off = 16; off > 0; off >>= 1) {
        p0 += __shfl_down_sync(0xFFFFFFFFu, p0, off);
        p1 += __shfl_down_sync(0xFFFFFFFFu, p1, off);
    }
    const int lane = tid & 31, wid = tid >> 5;
    if (lane == 0) { sred[wid] = p0; sred[8 + wid] = p1; }
    __syncthreads();
    if (tid == 0) {
        float s0 = 0.f, s1 = 0.f;
#pragma unroll
        for (int w = 0; w < 8; w++) { s0 += sred[w]; s1 += sred[8 + w]; }
        out[OUT_OFF + 2 * b]     = s0 + bout[0];
        out[OUT_OFF + 2 * b + 1] = s1 + bout[1];
    }
}

// ---------------------------------------------------------------------------
// Launch
// ---------------------------------------------------------------------------
extern "C" void kernel_launch(void* const* d_in, const int* in_sizes, int n_in,
                              void* d_out, int out_size)
{
    const float* r_att   = (const float*)d_in[0];
    const float* p_att   = (const float*)d_in[1];
    const float* r_fun   = (const float*)d_in[2];
    const float* p_fun   = (const float*)d_in[3];
    const int*   idx     = (const int*)  d_in[4];
    const float* W_att1  = (const float*)d_in[5];
    const float* b_att1  = (const float*)d_in[6];
    const float* W_att2  = (const float*)d_in[7];
    const float* b_att2  = (const float*)d_in[8];
    const float* W_fun1  = (const float*)d_in[9];
    const float* b_fun1  = (const float*)d_in[10];
    const float* W_fun2  = (const float*)d_in[11];
    const float* b_fun2  = (const float*)d_in[12];
    const float* conv1_w = (const float*)d_in[13];
    const float* conv1_b = (const float*)d_in[14];
    const float* conv2_w = (const float*)d_in[15];
    const float* conv2_b = (const float*)d_in[16];
    const float* W_out   = (const float*)d_in[17];
    const float* b_out   = (const float*)d_in[18];
    float* out = (float*)d_out;

    void* hid_p = nullptr;
    cudaGetSymbolAddress(&hid_p, g_hid);
    float* hid = (float*)hid_p;

    dim3 blk(256);

    // att MLP
    sgemm_k<128,128,8,8,0><<<dim3(N_ATT1/128, (M_TOT+127)/128), blk>>>(
        r_att, p_att, N_R, W_att1, b_att1, hid, M_TOT, N_ATT1, K_ATT, N_ATT1, 0);
    sgemm_k<64,64,4,4,1><<<dim3(N_E/64, (M_TOT+63)/64), blk>>>(
        hid, hid, M_TOT, W_att2, b_att2, out, M_TOT, N_E, N_ATT1, D_E, 0);

    // fun MLP
    sgemm_k<128,128,8,8,0><<<dim3(N_FUN1/128, (M_TOT+127)/128), blk>>>(
        r_fun, p_fun, N_R, W_fun1, b_fun1, hid, M_TOT, N_FUN1, K_FUN, N_FUN1, 0);
    sgemm_k<64,64,4,4,1><<<dim3(N_E/64, (M_TOT+63)/64), blk>>>(
        hid, hid, M_TOT, W_fun2, b_fun2, out, M_TOT, N_E, N_FUN1, D_E, N_E);

    // fused conv pipeline (reads e from d_out, writes output + flat)
    cudaFuncSetAttribute(conv_fused_kernel,
                         cudaFuncAttributeMaxDynamicSharedMemorySize,
                         CONV_SMEM_BYTES);
    conv_fused_kernel<<<BATCH, blk, CONV_SMEM_BYTES>>>(
        out, idx, conv1_w, conv1_b, conv2_w, conv2_b, W_out, b_out, out);
}

// round 7
// speedup vs baseline: 2.1782x; 2.1782x over previous
#include <cuda_runtime.h>
#include <cuda_bf16.h>
#include <math.h>
#include <stdint.h>

// ---------------------------------------------------------------------------
// Problem constants
// ---------------------------------------------------------------------------
#define N_R      2000
#define N_P      1512
#define M_TOT    3512
#define K_ATT    3000
#define N_ATT1   2048
#define K_FUN    5603
#define N_FUN1   4096
#define N_E      256
#define D_E      512
#define BATCH    8192
#define PROTEIN  1512

#define OUT_OFF  (M_TOT * D_E)
#define FLAT_OFF (OUT_OFF + BATCH * 2)

__device__ float g_hid[(size_t)M_TOT * N_FUN1];

// ---------------------------------------------------------------------------
// helpers
// ---------------------------------------------------------------------------
__device__ __forceinline__ uint32_t smem_u32(const void* p) {
    uint32_t a;
    asm("{ .reg .u64 t; cvta.to.shared.u64 t, %1; cvt.u32.u64 %0, t; }"
        : "=r"(a) : "l"(p));
    return a;
}

#define LDM4(r, a) \
    asm volatile("ldmatrix.sync.aligned.m8n8.x4.shared.b16 {%0,%1,%2,%3}, [%4];" \
                 : "=r"((r)[0]), "=r"((r)[1]), "=r"((r)[2]), "=r"((r)[3]) \
                 : "r"(a))

__device__ __forceinline__ void mma16816(float* d, const uint32_t* a,
                                         uint32_t b0, uint32_t b1) {
    asm volatile(
        "mma.sync.aligned.m16n8k16.row.col.f32.bf16.bf16.f32 "
        "{%0,%1,%2,%3}, {%4,%5,%6,%7}, {%8,%9}, {%0,%1,%2,%3};"
        : "+f"(d[0]), "+f"(d[1]), "+f"(d[2]), "+f"(d[3])
        : "r"(a[0]), "r"(a[1]), "r"(a[2]), "r"(a[3]), "r"(b0), "r"(b1));
}

__device__ __forceinline__ void cvt_hilo(float a, float b, uint32_t& hi, uint32_t& lo) {
    __nv_bfloat16 ah = __float2bfloat16(a);
    __nv_bfloat16 bh = __float2bfloat16(b);
    __nv_bfloat16 al = __float2bfloat16(a - __bfloat162float(ah));
    __nv_bfloat16 bl = __float2bfloat16(b - __bfloat162float(bh));
    hi = (uint32_t)__bfloat16_as_ushort(ah) | ((uint32_t)__bfloat16_as_ushort(bh) << 16);
    lo = (uint32_t)__bfloat16_as_ushort(al) | ((uint32_t)__bfloat16_as_ushort(bl) << 16);
}

// ---------------------------------------------------------------------------
// mma.sync GEMM: C[r*ldc+cOff+c] = act(sum_k A[r][k]*B[k][c] + bias[c])
// A = virtual concat of A0 (M0 rows) and A1.  Tile 128x128, BK=64,
// double-buffered smem, bf16 hi/lo 3-term split. EPI: 0 = GELU, 1 = sigmoid.
// smem stage (65536 B): Ah[128][64] | Al | Bh(n-major)[128][64] | Bl
// NOTE: A rows are only 16B-aligned when K%4==0 (K=5603 is NOT) -> scalar path.
// ---------------------------------------------------------------------------
#define STAGE_SZ 65536
#define MG_DSMEM (2 * STAGE_SZ)

template<int EPI>
__global__ void __launch_bounds__(256, 1)
mgemm(const float* __restrict__ A0, const float* __restrict__ A1, int M0,
      const float* __restrict__ Bm, const float* __restrict__ bias,
      float* __restrict__ C, int M, int N, int K, int ldc, int cOff)
{
    extern __shared__ __align__(128) char sm[];

    const int tid  = threadIdx.x;
    const int wid  = tid >> 5;
    const int lane = tid & 31;
    const int wm   = wid >> 1;           // 0..3
    const int wn   = wid & 1;            // 0..1
    const int bx = blockIdx.x, by = blockIdx.y;

    float acc[2][8][4];
#pragma unroll
    for (int i = 0; i < 2; i++)
#pragma unroll
        for (int j = 0; j < 8; j++)
#pragma unroll
            for (int q = 0; q < 4; q++) acc[i][j][q] = 0.f;

    // loader indices
    const int ar = tid >> 3;             // A: row within 32-row pass
    const int ac = tid & 7;              // A: chunk column (8 floats)
    const int bn = tid & 127;            // B: n-column owned
    const int bh = tid >> 7;             // B: k-half
    const int gn = bx * 128 + bn;

    const bool kAligned = ((K & 3) == 0);

    // staging registers
    float4 aS[4][2];
    float  bS[32];

    const int nt = (K + 63) >> 6;

    // ---- tile load into registers ----
    auto loadTile = [&](int kt) {
        const int k0 = kt * 64;
#pragma unroll
        for (int p = 0; p < 4; p++) {
            const int gr = by * 128 + p * 32 + ar;
            const float* rp = nullptr;
            if (gr < M) rp = (gr < M0) ? A0 + (size_t)gr * K
                                       : A1 + (size_t)(gr - M0) * K;
            const int kk = k0 + ac * 8;
            if (rp && kk + 8 <= K && kAligned) {
                aS[p][0] = *reinterpret_cast<const float4*>(rp + kk);
                aS[p][1] = *reinterpret_cast<const float4*>(rp + kk + 4);
            } else {
                float t[8];
#pragma unroll
                for (int i = 0; i < 8; i++)
                    t[i] = (rp && kk + i < K) ? rp[kk + i] : 0.f;
                aS[p][0] = make_float4(t[0], t[1], t[2], t[3]);
                aS[p][1] = make_float4(t[4], t[5], t[6], t[7]);
            }
        }
#pragma unroll
        for (int kk = 0; kk < 32; kk++) {
            const int k = k0 + bh * 32 + kk;
            bS[kk] = (k < K) ? Bm[(size_t)k * N + gn] : 0.f;
        }
    };

    // ---- convert + store registers into smem stage s ----
    auto storeTile = [&](int s) {
        char* base = sm + s * STAGE_SZ;
#pragma unroll
        for (int p = 0; p < 4; p++) {
            const int r = p * 32 + ar;
            const uint32_t off = (uint32_t)(r * 128 + ((ac ^ (r & 7)) << 4));
            uint32_t h[4], l[4];
            cvt_hilo(aS[p][0].x, aS[p][0].y, h[0], l[0]);
            cvt_hilo(aS[p][0].z, aS[p][0].w, h[1], l[1]);
            cvt_hilo(aS[p][1].x, aS[p][1].y, h[2], l[2]);
            cvt_hilo(aS[p][1].z, aS[p][1].w, h[3], l[3]);
            *reinterpret_cast<uint4*>(base + off)         = make_uint4(h[0], h[1], h[2], h[3]);
            *reinterpret_cast<uint4*>(base + 16384 + off) = make_uint4(l[0], l[1], l[2], l[3]);
        }
#pragma unroll
        for (int q = 0; q < 4; q++) {
            uint32_t h[4], l[4];
#pragma unroll
            for (int x = 0; x < 4; x++)
                cvt_hilo(bS[q * 8 + 2 * x], bS[q * 8 + 2 * x + 1], h[x], l[x]);
            const int c = bh * 4 + q;
            const uint32_t off = (uint32_t)(bn * 128 + ((c ^ (bn & 7)) << 4));
            *reinterpret_cast<uint4*>(base + 32768 + off) = make_uint4(h[0], h[1], h[2], h[3]);
            *reinterpret_cast<uint4*>(base + 49152 + off) = make_uint4(l[0], l[1], l[2], l[3]);
        }
    };

    // per-lane ldmatrix geometry
    const int arow0 = wm * 32 + (lane & 15);
    const int asel  = lane >> 4;
    const int bg    = lane >> 3;
    const int brow0 = wn * 64 + (lane & 7) + ((bg >> 1) << 3);
    const int bsel  = bg & 1;

    auto compute = [&](int s) {
        const uint32_t base = smem_u32(sm + s * STAGE_SZ);
        const uint32_t pAh = base;
        const uint32_t pAl = base + 16384;
        const uint32_t pBh = base + 32768;
        const uint32_t pBl = base + 49152;
#pragma unroll
        for (int ks = 0; ks < 4; ks++) {
            uint32_t ah[2][4], al[2][4];
#pragma unroll
            for (int i = 0; i < 2; i++) {
                const int r = arow0 + i * 16;
                const uint32_t off =
                    (uint32_t)(r * 128 + (((ks * 2 + asel) ^ (r & 7)) << 4));
                LDM4(ah[i], pAh + off);
                LDM4(al[i], pAl + off);
            }
#pragma unroll
            for (int j2 = 0; j2 < 4; j2++) {
                const int r = brow0 + j2 * 16;
                const uint32_t off =
                    (uint32_t)(r * 128 + (((ks * 2 + bsel) ^ (r & 7)) << 4));
                uint32_t bhr[4], blr[4];
                LDM4(bhr, pBh + off);
                LDM4(blr, pBl + off);
#pragma unroll
                for (int i = 0; i < 2; i++) {
                    mma16816(acc[i][2 * j2],     ah[i], bhr[0], bhr[1]);
                    mma16816(acc[i][2 * j2 + 1], ah[i], bhr[2], bhr[3]);
                    mma16816(acc[i][2 * j2],     ah[i], blr[0], blr[1]);
                    mma16816(acc[i][2 * j2 + 1], ah[i], blr[2], blr[3]);
                    mma16816(acc[i][2 * j2],     al[i], bhr[0], bhr[1]);
                    mma16816(acc[i][2 * j2 + 1], al[i], bhr[2], bhr[3]);
                }
            }
        }
    };

    // ---- pipelined main loop ----
    loadTile(0);
    storeTile(0);
    __syncthreads();
    for (int t = 0; t < nt; t++) {
        if (t + 1 < nt) loadTile(t + 1);
        compute(t & 1);
        if (t + 1 < nt) storeTile((t + 1) & 1);
        __syncthreads();
    }

    // ---- epilogue ----
    const int qr = lane >> 2;
    const int qc = (lane & 3) * 2;
    const float* bp = bias + bx * 128 + wn * 64;
#pragma unroll
    for (int i = 0; i < 2; i++) {
#pragma unroll
        for (int rr = 0; rr < 2; rr++) {
            const int gr = by * 128 + wm * 32 + i * 16 + rr * 8 + qr;
            if (gr >= M) continue;
            float* cp = C + (size_t)gr * ldc + cOff + bx * 128 + wn * 64;
#pragma unroll
            for (int j = 0; j < 8; j++) {
                float x0 = acc[i][j][rr * 2 + 0] + bp[j * 8 + qc];
                float x1 = acc[i][j][rr * 2 + 1] + bp[j * 8 + qc + 1];
                if (EPI == 0) {
                    x0 = 0.5f * x0 * (1.0f + erff(x0 * 0.70710678118654752440f));
                    x1 = 0.5f * x1 * (1.0f + erff(x1 * 0.70710678118654752440f));
                } else {
                    x0 = 1.0f / (1.0f + expf(-x0));
                    x1 = 1.0f / (1.0f + expf(-x1));
                }
                *reinterpret_cast<float2*>(cp + j * 8 + qc) = make_float2(x0, x1);
            }
        }
    }
}

// ---------------------------------------------------------------------------
// Fused per-sample conv pipeline (unchanged from passing round)
// ---------------------------------------------------------------------------
#define OFF_SX    0
#define OFF_SH1   1032
#define OFF_SW1   (OFF_SH1 + 8320)
#define OFF_SB1   (OFF_SW1 + 240)
#define OFF_SW2T  (OFF_SB1 + 16)
#define OFF_SB2   (OFF_SW2T + 7680)
#define OFF_SFLAT (OFF_SB2 + 32)
#define OFF_SRED  (OFF_SFLAT + 8320)
#define CONV_SMEM_FLOATS (OFF_SRED + 16)
#define CONV_SMEM_BYTES  (CONV_SMEM_FLOATS * 4)

__device__ __forceinline__ float leaky_f(float x) { return fmaxf(x, 0.01f * x); }

__global__ void __launch_bounds__(256)
conv_fused_kernel(const float* __restrict__ e,
                  const int*   __restrict__ idx,
                  const float* __restrict__ w1,
                  const float* __restrict__ b1,
                  const float* __restrict__ w2,
                  const float* __restrict__ b2,
                  const float* __restrict__ Wout,
                  const float* __restrict__ bout,
                  float* __restrict__ out)
{
    extern __shared__ float smf[];
    float* sx    = smf + OFF_SX;
    float* sh1   = smf + OFF_SH1;
    float* sw1   = smf + OFF_SW1;
    float* sb1   = smf + OFF_SB1;
    float* sw2t  = smf + OFF_SW2T;
    float* sb2   = smf + OFF_SB2;
    float* sflat = smf + OFF_SFLAT;
    float* sred  = smf + OFF_SRED;

    const int tid = threadIdx.x;
    const int b   = blockIdx.x;

    const int id0  = idx[b];
    const int r_no = id0 / PROTEIN;
    const int p_no = id0 % PROTEIN;
    const float* er = e + (size_t)r_no * D_E;
    const float* ep = e + (size_t)(N_R + p_no) * D_E;
    for (int i = tid; i < D_E; i += 256) {
        sx[2 + i]       = er[i];
        sx[516 + 2 + i] = ep[i];
    }
    if (tid < 2) {
        float* row = sx + tid * 516;
        row[0] = 0.f; row[1] = 0.f; row[514] = 0.f; row[515] = 0.f;
    }
    for (int i = tid; i < 240; i += 256) sw1[i] = w1[i];
    if (tid < 16) sb1[tid] = b1[tid];
    for (int i = tid; i < 7680; i += 256) {
        int c  = i / 240;
        int ci = (i % 240) / 15;
        int kh = (i % 15) / 5;
        int kw = i % 5;
        sw2t[((kh * 5 + kw) * 16 + ci) * 32 + c] = w2[i];
    }
    if (tid < 32) sb2[tid] = b2[tid];
    __syncthreads();

    for (int j = 0; j < 32; j++) {
        const int co = j >> 1;
        const int hh = j & 1;
        const int pw = tid;
        const float* P = sx + hh * 516 + 2 * pw;
        const float* Q = sx + (1 - hh) * 516 + 2 * pw;
        const float* wrow = sw1 + co * 15;
        const int qrow = 2 - 2 * hh;
        float wD[5], wQ[5];
#pragma unroll
        for (int t = 0; t < 5; t++) { wD[t] = wrow[5 + t]; wQ[t] = wrow[qrow * 5 + t]; }
        float p[6], q[6];
#pragma unroll
        for (int t = 0; t < 6; t++) { p[t] = P[t]; q[t] = Q[t]; }
        const float bz = sb1[co];
        float d0 = bz, d1 = bz, s0 = bz, s1 = bz;
#pragma unroll
        for (int kw = 0; kw < 5; kw++) {
            d0 = fmaf(p[kw],   wD[kw], d0); d0 = fmaf(q[kw],   wQ[kw], d0);
            d1 = fmaf(p[kw+1], wD[kw], d1); d1 = fmaf(q[kw+1], wQ[kw], d1);
            s0 = fmaf(p[kw],   wQ[kw], s0);
            s1 = fmaf(p[kw+1], wQ[kw], s1);
        }
        float v = 0.25f * (leaky_f(d0) + leaky_f(d1) + leaky_f(s0) + leaky_f(s1));
        sh1[(co * 2 + hh) * 260 + 2 + pw] = v;
    }
    if (tid < 32) {
        float* row = sh1 + tid * 260;
        row[0] = 0.f; row[1] = 0.f; row[258] = 0.f; row[259] = 0.f;
    }
    __syncthreads();

    {
        const int c   = tid & 31;
        const int hh  = (tid >> 5) & 1;
        const int pwb = tid >> 6;
        const float bz2 = sb2[c];
        const int qk = 2 - 2 * hh;

        for (int g = 0; g < 8; g++) {
            const int pw0 = pwb * 32 + g * 4;
            float aD0[4], aD1[4], aS0[4], aS1[4];
#pragma unroll
            for (int p2 = 0; p2 < 4; p2++) { aD0[p2]=bz2; aD1[p2]=bz2; aS0[p2]=bz2; aS1[p2]=bz2; }

            for (int ci = 0; ci < 16; ci++) {
                const float* rowP = sh1 + (ci * 2 + hh) * 260 + 2 * pw0;
                const float* rowQ = sh1 + (ci * 2 + (1 - hh)) * 260 + 2 * pw0;
                float P[12], Q[12];
#pragma unroll
                for (int t = 0; t < 12; t++) { P[t] = rowP[t]; Q[t] = rowQ[t]; }
                float wD[5], wQ[5];
#pragma unroll
                for (int t = 0; t < 5; t++) {
                    wD[t] = sw2t[((5 + t) * 16 + ci) * 32 + c];
                    wQ[t] = sw2t[((qk * 5 + t) * 16 + ci) * 32 + c];
                }
#pragma unroll
                for (int p2 = 0; p2 < 4; p2++) {
#pragma unroll
                    for (int kw = 0; kw < 5; kw++) {
                        const float pv  = P[2*p2 + kw];
                        const float pv1 = P[2*p2 + 1 + kw];
                        const float qv  = Q[2*p2 + kw];
                        const float qv1 = Q[2*p2 + 1 + kw];
                        aD0[p2] = fmaf(pv,  wD[kw], aD0[p2]);
                        aD0[p2] = fmaf(qv,  wQ[kw], aD0[p2]);
                        aD1[p2] = fmaf(pv1, wD[kw], aD1[p2]);
                        aD1[p2] = fmaf(qv1, wQ[kw], aD1[p2]);
                        aS0[p2] = fmaf(pv,  wQ[kw], aS0[p2]);
                        aS1[p2] = fmaf(pv1, wQ[kw], aS1[p2]);
                    }
                }
            }
#pragma unroll
            for (int p2 = 0; p2 < 4; p2++) {
                float m = fmaxf(fmaxf(aD0[p2], aD1[p2]), fmaxf(aS0[p2], aS1[p2]));
                float v = tanhf(leaky_f(m));
                sflat[(pw0 + p2) * 65 + hh * 32 + c] = v;
            }
        }
    }
    __syncthreads();

    float p0 = 0.f, p1 = 0.f;
    float* flatOut = out + FLAT_OFF + (size_t)b * 8192;
    for (int j = 0; j < 32; j++) {
        const int o  = j * 256 + tid;
        const int pw = o & 127;
        const int hh = (o >> 7) & 1;
        const int c  = o >> 8;
        const float v = sflat[pw * 65 + hh * 32 + c];
        flatOut[o] = v;
        p0 = fmaf(v, Wout[2 * o],     p0);
        p1 = fmaf(v, Wout[2 * o + 1], p1);
    }
#pragma unroll
    for (int off = 16; off > 0; off >>= 1) {
        p0 += __shfl_down_sync(0xFFFFFFFFu, p0, off);
        p1 += __shfl_down_sync(0xFFFFFFFFu, p1, off);
    }
    const int lane = tid & 31, wrp = tid >> 5;
    if (lane == 0) { sred[wrp] = p0; sred[8 + wrp] = p1; }
    __syncthreads();
    if (tid == 0) {
        float s0 = 0.f, s1 = 0.f;
#pragma unroll
        for (int w = 0; w < 8; w++) { s0 += sred[w]; s1 += sred[8 + w]; }
        out[OUT_OFF + 2 * b]     = s0 + bout[0];
        out[OUT_OFF + 2 * b + 1] = s1 + bout[1];
    }
}

// ---------------------------------------------------------------------------
// Launch
// ---------------------------------------------------------------------------
extern "C" void kernel_launch(void* const* d_in, const int* in_sizes, int n_in,
                              void* d_out, int out_size)
{
    const float* r_att   = (const float*)d_in[0];
    const float* p_att   = (const float*)d_in[1];
    const float* r_fun   = (const float*)d_in[2];
    const float* p_fun   = (const float*)d_in[3];
    const int*   idx     = (const int*)  d_in[4];
    const float* W_att1  = (const float*)d_in[5];
    const float* b_att1  = (const float*)d_in[6];
    const float* W_att2  = (const float*)d_in[7];
    const float* b_att2  = (const float*)d_in[8];
    const float* W_fun1  = (const float*)d_in[9];
    const float* b_fun1  = (const float*)d_in[10];
    const float* W_fun2  = (const float*)d_in[11];
    const float* b_fun2  = (const float*)d_in[12];
    const float* conv1_w = (const float*)d_in[13];
    const float* conv1_b = (const float*)d_in[14];
    const float* conv2_w = (const float*)d_in[15];
    const float* conv2_b = (const float*)d_in[16];
    const float* W_out   = (const float*)d_in[17];
    const float* b_out   = (const float*)d_in[18];
    float* out = (float*)d_out;

    void* hid_p = nullptr;
    cudaGetSymbolAddress(&hid_p, g_hid);
    float* hid = (float*)hid_p;

    cudaFuncSetAttribute(mgemm<0>, cudaFuncAttributeMaxDynamicSharedMemorySize, MG_DSMEM);
    cudaFuncSetAttribute(mgemm<1>, cudaFuncAttributeMaxDynamicSharedMemorySize, MG_DSMEM);
    cudaFuncSetAttribute(conv_fused_kernel,
                         cudaFuncAttributeMaxDynamicSharedMemorySize, CONV_SMEM_BYTES);

    dim3 blk(256);
    const int mtiles = (M_TOT + 127) / 128;   // 28

    // att MLP
    mgemm<0><<<dim3(N_ATT1 / 128, mtiles), blk, MG_DSMEM>>>(
        r_att, p_att, N_R, W_att1, b_att1, hid, M_TOT, N_ATT1, K_ATT, N_ATT1, 0);
    mgemm<1><<<dim3(N_E / 128, mtiles), blk, MG_DSMEM>>>(
        hid, hid, M_TOT, W_att2, b_att2, out, M_TOT, N_E, N_ATT1, D_E, 0);

    // fun MLP
    mgemm<0><<<dim3(N_FUN1 / 128, mtiles), blk, MG_DSMEM>>>(
        r_fun, p_fun, N_R, W_fun1, b_fun1, hid, M_TOT, N_FUN1, K_FUN, N_FUN1, 0);
    mgemm<1><<<dim3(N_E / 128, mtiles), blk, MG_DSMEM>>>(
        hid, hid, M_TOT, W_fun2, b_fun2, out, M_TOT, N_E, N_FUN1, D_E, N_E);

    // fused conv pipeline
    conv_fused_kernel<<<BATCH, blk, CONV_SMEM_BYTES>>>(
        out, idx, conv1_w, conv1_b, conv2_w, conv2_b, W_out, b_out, out);
}

// round 10
// speedup vs baseline: 2.3987x; 1.1013x over previous
#include <cuda_runtime.h>
#include <cuda_bf16.h>
#include <math.h>
#include <stdint.h>

// ---------------------------------------------------------------------------
// Problem constants
// ---------------------------------------------------------------------------
#define N_R      2000
#define N_P      1512
#define M_TOT    3512
#define K_ATT    3000
#define N_ATT1   2048
#define K_FUN    5603
#define N_FUN1   4096
#define N_E      256
#define D_E      512
#define BATCH    8192
#define PROTEIN  1512

#define OUT_OFF  (M_TOT * D_E)
#define FLAT_OFF (OUT_OFF + BATCH * 2)

__device__ float g_hid[(size_t)M_TOT * N_FUN1];

// ---------------------------------------------------------------------------
// helpers
// ---------------------------------------------------------------------------
__device__ __forceinline__ uint32_t smem_u32(const void* p) {
    uint32_t a;
    asm("{ .reg .u64 t; cvta.to.shared.u64 t, %1; cvt.u32.u64 %0, t; }"
        : "=r"(a) : "l"(p));
    return a;
}

#define LDM4(r, a) \
    asm volatile("ldmatrix.sync.aligned.m8n8.x4.shared.b16 {%0,%1,%2,%3}, [%4];" \
                 : "=r"((r)[0]), "=r"((r)[1]), "=r"((r)[2]), "=r"((r)[3]) \
                 : "r"(a))

__device__ __forceinline__ void mma16816(float* d, const uint32_t* a,
                                         uint32_t b0, uint32_t b1) {
    asm volatile(
        "mma.sync.aligned.m16n8k16.row.col.f32.bf16.bf16.f32 "
        "{%0,%1,%2,%3}, {%4,%5,%6,%7}, {%8,%9}, {%0,%1,%2,%3};"
        : "+f"(d[0]), "+f"(d[1]), "+f"(d[2]), "+f"(d[3])
        : "r"(a[0]), "r"(a[1]), "r"(a[2]), "r"(a[3]), "r"(b0), "r"(b1));
}

__device__ __forceinline__ void cvt_hilo(float a, float b, uint32_t& hi, uint32_t& lo) {
    __nv_bfloat16 ah = __float2bfloat16(a);
    __nv_bfloat16 bh = __float2bfloat16(b);
    __nv_bfloat16 al = __float2bfloat16(a - __bfloat162float(ah));
    __nv_bfloat16 bl = __float2bfloat16(b - __bfloat162float(bh));
    hi = (uint32_t)__bfloat16_as_ushort(ah) | ((uint32_t)__bfloat16_as_ushort(bh) << 16);
    lo = (uint32_t)__bfloat16_as_ushort(al) | ((uint32_t)__bfloat16_as_ushort(bl) << 16);
}

__device__ __forceinline__ float leaky_f(float x) { return fmaxf(x, 0.01f * x); }

// ---------------------------------------------------------------------------
// mma.sync GEMM (unchanged; grid: x = M-tiles fast -> B-tile L2 reuse)
// ---------------------------------------------------------------------------
#define STAGE_SZ 65536
#define MG_DSMEM (2 * STAGE_SZ)

template<int EPI>
__global__ void __launch_bounds__(256, 1)
mgemm(const float* __restrict__ A0, const float* __restrict__ A1, int M0,
      const float* __restrict__ Bm, const float* __restrict__ bias,
      float* __restrict__ C, int M, int N, int K, int ldc, int cOff)
{
    extern __shared__ __align__(128) char sm[];

    const int tid  = threadIdx.x;
    const int wid  = tid >> 5;
    const int lane = tid & 31;
    const int wm   = wid >> 1;
    const int wn   = wid & 1;
    const int bx = blockIdx.y;      // N-tile (slow axis)
    const int by = blockIdx.x;      // M-tile (fast axis)

    float acc[2][8][4];
#pragma unroll
    for (int i = 0; i < 2; i++)
#pragma unroll
        for (int j = 0; j < 8; j++)
#pragma unroll
            for (int q = 0; q < 4; q++) acc[i][j][q] = 0.f;

    const int ar = tid >> 3;
    const int ac = tid & 7;
    const int bn = tid & 127;
    const int bh = tid >> 7;
    const int gn = bx * 128 + bn;

    const bool kAligned = ((K & 3) == 0);

    float4 aS[4][2];
    float  bS[32];

    const int nt = (K + 63) >> 6;

    auto loadTile = [&](int kt) {
        const int k0 = kt * 64;
#pragma unroll
        for (int p = 0; p < 4; p++) {
            const int gr = by * 128 + p * 32 + ar;
            const float* rp = nullptr;
            if (gr < M) rp = (gr < M0) ? A0 + (size_t)gr * K
                                       : A1 + (size_t)(gr - M0) * K;
            const int kk = k0 + ac * 8;
            if (rp && kk + 8 <= K && kAligned) {
                aS[p][0] = *reinterpret_cast<const float4*>(rp + kk);
                aS[p][1] = *reinterpret_cast<const float4*>(rp + kk + 4);
            } else {
                float t[8];
#pragma unroll
                for (int i = 0; i < 8; i++)
                    t[i] = (rp && kk + i < K) ? rp[kk + i] : 0.f;
                aS[p][0] = make_float4(t[0], t[1], t[2], t[3]);
                aS[p][1] = make_float4(t[4], t[5], t[6], t[7]);
            }
        }
#pragma unroll
        for (int kk = 0; kk < 32; kk++) {
            const int k = k0 + bh * 32 + kk;
            bS[kk] = (k < K) ? Bm[(size_t)k * N + gn] : 0.f;
        }
    };

    auto storeTile = [&](int s) {
        char* base = sm + s * STAGE_SZ;
#pragma unroll
        for (int p = 0; p < 4; p++) {
            const int r = p * 32 + ar;
            const uint32_t off = (uint32_t)(r * 128 + ((ac ^ (r & 7)) << 4));
            uint32_t h[4], l[4];
            cvt_hilo(aS[p][0].x, aS[p][0].y, h[0], l[0]);
            cvt_hilo(aS[p][0].z, aS[p][0].w, h[1], l[1]);
            cvt_hilo(aS[p][1].x, aS[p][1].y, h[2], l[2]);
            cvt_hilo(aS[p][1].z, aS[p][1].w, h[3], l[3]);
            *reinterpret_cast<uint4*>(base + off)         = make_uint4(h[0], h[1], h[2], h[3]);
            *reinterpret_cast<uint4*>(base + 16384 + off) = make_uint4(l[0], l[1], l[2], l[3]);
        }
#pragma unroll
        for (int q = 0; q < 4; q++) {
            uint32_t h[4], l[4];
#pragma unroll
            for (int x = 0; x < 4; x++)
                cvt_hilo(bS[q * 8 + 2 * x], bS[q * 8 + 2 * x + 1], h[x], l[x]);
            const int c = bh * 4 + q;
            const uint32_t off = (uint32_t)(bn * 128 + ((c ^ (bn & 7)) << 4));
            *reinterpret_cast<uint4*>(base + 32768 + off) = make_uint4(h[0], h[1], h[2], h[3]);
            *reinterpret_cast<uint4*>(base + 49152 + off) = make_uint4(l[0], l[1], l[2], l[3]);
        }
    };

    const int arow0 = wm * 32 + (lane & 15);
    const int asel  = lane >> 4;
    const int bg    = lane >> 3;
    const int brow0 = wn * 64 + (lane & 7) + ((bg >> 1) << 3);
    const int bsel  = bg & 1;

    auto compute = [&](int s) {
        const uint32_t base = smem_u32(sm + s * STAGE_SZ);
        const uint32_t pAh = base;
        const uint32_t pAl = base + 16384;
        const uint32_t pBh = base + 32768;
        const uint32_t pBl = base + 49152;
#pragma unroll
        for (int ks = 0; ks < 4; ks++) {
            uint32_t ah[2][4], al[2][4];
#pragma unroll
            for (int i = 0; i < 2; i++) {
                const int r = arow0 + i * 16;
                const uint32_t off =
                    (uint32_t)(r * 128 + (((ks * 2 + asel) ^ (r & 7)) << 4));
                LDM4(ah[i], pAh + off);
                LDM4(al[i], pAl + off);
            }
#pragma unroll
            for (int j2 = 0; j2 < 4; j2++) {
                const int r = brow0 + j2 * 16;
                const uint32_t off =
                    (uint32_t)(r * 128 + (((ks * 2 + bsel) ^ (r & 7)) << 4));
                uint32_t bhr[4], blr[4];
                LDM4(bhr, pBh + off);
                LDM4(blr, pBl + off);
#pragma unroll
                for (int i = 0; i < 2; i++) {
                    mma16816(acc[i][2 * j2],     ah[i], bhr[0], bhr[1]);
                    mma16816(acc[i][2 * j2 + 1], ah[i], bhr[2], bhr[3]);
                    mma16816(acc[i][2 * j2],     ah[i], blr[0], blr[1]);
                    mma16816(acc[i][2 * j2 + 1], ah[i], blr[2], blr[3]);
                    mma16816(acc[i][2 * j2],     al[i], bhr[0], bhr[1]);
                    mma16816(acc[i][2 * j2 + 1], al[i], bhr[2], bhr[3]);
                }
            }
        }
    };

    loadTile(0);
    storeTile(0);
    __syncthreads();
    for (int t = 0; t < nt; t++) {
        if (t + 1 < nt) loadTile(t + 1);
        compute(t & 1);
        if (t + 1 < nt) storeTile((t + 1) & 1);
        __syncthreads();
    }

    const int qr = lane >> 2;
    const int qc = (lane & 3) * 2;
    const float* bp = bias + bx * 128 + wn * 64;
#pragma unroll
    for (int i = 0; i < 2; i++) {
#pragma unroll
        for (int rr = 0; rr < 2; rr++) {
            const int gr = by * 128 + wm * 32 + i * 16 + rr * 8 + qr;
            if (gr >= M) continue;
            float* cp = C + (size_t)gr * ldc + cOff + bx * 128 + wn * 64;
#pragma unroll
            for (int j = 0; j < 8; j++) {
                float x0 = acc[i][j][rr * 2 + 0] + bp[j * 8 + qc];
                float x1 = acc[i][j][rr * 2 + 1] + bp[j * 8 + qc + 1];
                if (EPI == 0) {
                    x0 = 0.5f * x0 * (1.0f + erff(x0 * 0.70710678118654752440f));
                    x1 = 0.5f * x1 * (1.0f + erff(x1 * 0.70710678118654752440f));
                } else {
                    x0 = 1.0f / (1.0f + expf(-x0));
                    x1 = 1.0f / (1.0f + expf(-x1));
                }
                *reinterpret_cast<float2*>(cp + j * 8 + qc) = make_float2(x0, x1);
            }
        }
    }
}

// ---------------------------------------------------------------------------
// Fused conv pipeline v2b: conv1 scalar -> conv2 via mma.sync bf16 hi/lo.
// One CTA (256 thr = 8 warps) per sample.
// Pooled pre-tanh partials are stored in a DEDICATED FP32 buffer (bf16
// partials in v2 injected ~0.3% error into flat -> output failed 1e-3).
//
// smem byte layout (total 171488):
//   [0,      4128)  sx  (2*516 f32)
//   [4128,  37408)  sh1 (16*2*260 f32)
//   [37408, 62368)  A_in hi: 520 rows * 48B
//   [62368, 87328)  A_in lo
//   [87328,102688)  W stage: 15 slots * 32 rows * 32B (hi then lo)
//   [102688,103904) sw1(240) sb1(16) sb2(32) sred(16) f32
//   [103904,171488) partials f32: [t(4)][c(32)][132]
// ---------------------------------------------------------------------------
#define CV_SH1_F   1032
#define CV_AH_B    37408
#define CV_AL_B    62368
#define CV_W_B     87328
#define CV_W1_F    25672
#define CV_PART_F  25976
#define CV_SMEM_BYTES (171488)

__global__ void __launch_bounds__(256, 1)
conv_fused_v2(const float* __restrict__ e,
              const int*   __restrict__ idx,
              const float* __restrict__ w1,
              const float* __restrict__ b1,
              const float* __restrict__ w2,
              const float* __restrict__ b2,
              const float* __restrict__ Wout,
              const float* __restrict__ bout,
              float* __restrict__ out)
{
    extern __shared__ __align__(128) char smb[];
    float* smf = (float*)smb;
    float* sx  = smf;
    float* sh1 = smf + CV_SH1_F;
    float* sw1 = smf + CV_W1_F;
    float* sb1 = sw1 + 240;
    float* sb2 = sb1 + 16;
    float* sred = sb2 + 32;
    float* partf = smf + CV_PART_F;     // dedicated fp32 partials

    const int tid  = threadIdx.x;
    const int wid  = tid >> 5;
    const int lane = tid & 31;
    const int b    = blockIdx.x;

    // ---------------- S0: gather + small weights + W-hi staging -----------
    const int id0  = idx[b];
    const int r_no = id0 / PROTEIN;
    const int p_no = id0 % PROTEIN;
    const float* er = e + (size_t)r_no * D_E;
    const float* ep = e + (size_t)(N_R + p_no) * D_E;
    for (int i = tid; i < D_E; i += 256) {
        sx[2 + i]       = er[i];
        sx[516 + 2 + i] = ep[i];
    }
    if (tid < 2) {
        float* row = sx + tid * 516;
        row[0] = 0.f; row[1] = 0.f; row[514] = 0.f; row[515] = 0.f;
    }
    for (int i = tid; i < 240; i += 256) sw1[i] = w1[i];
    if (tid < 16) sb1[tid] = b1[tid];
    if (tid < 32) sb2[tid] = b2[tid];
    for (int i = tid; i < 7680; i += 256) {
        int c  = i / 240;
        int ci = (i % 240) / 15;
        int kh = (i % 15) / 5;
        int kw = i % 5;
        __nv_bfloat16 h = __float2bfloat16(w2[i]);
        *(__nv_bfloat16*)(smb + CV_W_B + (kh * 5 + kw) * 1024 + c * 32 + ci * 2) = h;
    }
    __syncthreads();

    // ---------------- S1: conv1 + leaky + avgpool -> sh1 ------------------
    for (int j = 0; j < 32; j++) {
        const int co = j >> 1;
        const int hh = j & 1;
        const int pw = tid;
        const float* P = sx + hh * 516 + 2 * pw;
        const float* Q = sx + (1 - hh) * 516 + 2 * pw;
        const float* wrow = sw1 + co * 15;
        const int qrow = 2 - 2 * hh;
        float wD[5], wQ[5];
#pragma unroll
        for (int t = 0; t < 5; t++) { wD[t] = wrow[5 + t]; wQ[t] = wrow[qrow * 5 + t]; }
        float p[6], q[6];
#pragma unroll
        for (int t = 0; t < 6; t++) { p[t] = P[t]; q[t] = Q[t]; }
        const float bz = sb1[co];
        float d0 = bz, d1 = bz, s0 = bz, s1 = bz;
#pragma unroll
        for (int kw = 0; kw < 5; kw++) {
            d0 = fmaf(p[kw],   wD[kw], d0); d0 = fmaf(q[kw],   wQ[kw], d0);
            d1 = fmaf(p[kw+1], wD[kw], d1); d1 = fmaf(q[kw+1], wQ[kw], d1);
            s0 = fmaf(p[kw],   wQ[kw], s0);
            s1 = fmaf(p[kw+1], wQ[kw], s1);
        }
        float v = 0.25f * (leaky_f(d0) + leaky_f(d1) + leaky_f(s0) + leaky_f(s1));
        sh1[(co * 2 + hh) * 260 + 2 + pw] = v;
    }
    if (tid < 32) {
        float* row = sh1 + tid * 260;
        row[0] = 0.f; row[1] = 0.f; row[258] = 0.f; row[259] = 0.f;
    }
    __syncthreads();

    // warp geometry for conv2 MMA
    const int t4  = wid >> 1;           // conv output row t (0..3)
    const int n16 = wid & 1;            // channel half
    const int kh0 = (t4 == 0) ? 2 : (t4 == 1) ? 1 : 0;
    const int nkh = (t4 == 1 || t4 == 2) ? 2 : 1;

    const uint32_t wbase  = smem_u32(smb) + CV_W_B;
    const uint32_t aHbase = smem_u32(smb) + CV_AH_B;
    const uint32_t aLbase = smem_u32(smb) + CV_AL_B;
    const uint32_t wrowoff =
        (uint32_t)((n16 * 16 + (lane & 7) + ((lane >> 4) << 3)) * 32 +
                   (((lane >> 3) & 1) << 4));

    uint32_t wf[2][10][4];

    // ---------------- S2: load W-hi frags; build A_in planes --------------
#pragma unroll
    for (int ee = 0; ee < 2; ee++) {
        if (ee < nkh) {
            const int kh = kh0 + ee;
#pragma unroll
            for (int kw = 0; kw < 5; kw++) {
                LDM4(wf[0][ee * 5 + kw], wbase + (kh * 5 + kw) * 1024 + wrowoff);
            }
        }
    }
    for (int i = tid; i < 520 * 8; i += 256) {
        const int r = i >> 3, q = i & 7;
        const int hp = (r >= 260) ? 1 : 0;
        const int j = r - hp * 260;
        const float v0 = sh1[((2 * q)     * 2 + hp) * 260 + j];
        const float v1 = sh1[((2 * q + 1) * 2 + hp) * 260 + j];
        uint32_t hi, lo;
        cvt_hilo(v0, v1, hi, lo);
        *(uint32_t*)(smb + CV_AH_B + r * 48 + q * 4) = hi;
        *(uint32_t*)(smb + CV_AL_B + r * 48 + q * 4) = lo;
    }
    __syncthreads();

    // ---------------- S3: restage W-lo; load frags ------------------------
    for (int i = tid; i < 7680; i += 256) {
        int c  = i / 240;
        int ci = (i % 240) / 15;
        int kh = (i % 15) / 5;
        int kw = i % 5;
        float v = w2[i];
        __nv_bfloat16 h = __float2bfloat16(v);
        __nv_bfloat16 l = __float2bfloat16(v - __bfloat162float(h));
        *(__nv_bfloat16*)(smb + CV_W_B + (kh * 5 + kw) * 1024 + c * 32 + ci * 2) = l;
    }
    __syncthreads();
#pragma unroll
    for (int ee = 0; ee < 2; ee++) {
        if (ee < nkh) {
            const int kh = kh0 + ee;
#pragma unroll
            for (int kw = 0; kw < 5; kw++) {
                LDM4(wf[1][ee * 5 + kw], wbase + (kh * 5 + kw) * 1024 + wrowoff);
            }
        }
    }

    // ---------------- S4: conv2 MMA + leaky + pair-max -> fp32 partials ---
    {
        const int r    = lane >> 2;          // 0..7
        const int c2   = (lane & 3) * 2;
        const float bzA0 = sb2[n16 * 16 + c2];
        const float bzA1 = sb2[n16 * 16 + c2 + 1];
        const float bzB0 = sb2[n16 * 16 + 8 + c2];
        const float bzB1 = sb2[n16 * 16 + 8 + c2 + 1];
        const uint32_t alOff = (uint32_t)((lane & 15) * 48 + ((lane >> 4) << 4));

        for (int m = 0; m < 16; m++) {
            const int w0 = m * 16;
            float a0[4] = {0.f, 0.f, 0.f, 0.f};
            float a1[4] = {0.f, 0.f, 0.f, 0.f};
#pragma unroll
            for (int ee = 0; ee < 2; ee++) {
                if (ee < nkh) {
                    const int hp = t4 + (kh0 + ee) - 2;    // 0 or 1
                    const uint32_t rb = (uint32_t)((hp * 260 + w0) * 48) + alOff;
#pragma unroll
                    for (int kw = 0; kw < 5; kw++) {
                        const uint32_t ab = rb + (uint32_t)(kw * 48);
                        uint32_t ah[4], al[4];
                        LDM4(ah, aHbase + ab);
                        LDM4(al, aLbase + ab);
                        const uint32_t* wh = wf[0][ee * 5 + kw];
                        const uint32_t* wl = wf[1][ee * 5 + kw];
                        mma16816(a0, ah, wh[0], wh[1]);
                        mma16816(a1, ah, wh[2], wh[3]);
                        mma16816(a0, ah, wl[0], wl[1]);
                        mma16816(a1, ah, wl[2], wl[3]);
                        mma16816(a0, al, wh[0], wh[1]);
                        mma16816(a1, al, wh[2], wh[3]);
                    }
                }
            }
#pragma unroll
            for (int j = 0; j < 2; j++) {
                float* ac = j ? a1 : a0;
                const float z0 = j ? bzB0 : bzA0;
                const float z1 = j ? bzB1 : bzA1;
                float m0 = leaky_f(ac[0] + z0);
                float m1 = leaky_f(ac[1] + z1);
                float m2 = leaky_f(ac[2] + z0);
                float m3 = leaky_f(ac[3] + z1);
                m0 = fmaxf(m0, __shfl_xor_sync(0xFFFFFFFFu, m0, 4));
                m1 = fmaxf(m1, __shfl_xor_sync(0xFFFFFFFFu, m1, 4));
                m2 = fmaxf(m2, __shfl_xor_sync(0xFFFFFFFFu, m2, 4));
                m3 = fmaxf(m3, __shfl_xor_sync(0xFFFFFFFFu, m3, 4));
                if ((r & 1) == 0) {
                    const int c0 = n16 * 16 + j * 8 + c2;
                    const int pwA = (w0 + r) >> 1;
                    const int pwB = (w0 + 8 + r) >> 1;
                    partf[(t4 * 32 + c0    ) * 132 + pwA] = m0;
                    partf[(t4 * 32 + c0 + 1) * 132 + pwA] = m1;
                    partf[(t4 * 32 + c0    ) * 132 + pwB] = m2;
                    partf[(t4 * 32 + c0 + 1) * 132 + pwB] = m3;
                }
            }
        }
    }
    __syncthreads();

    // ---------------- S5: cross-row max + tanh + flat + W_out -------------
    float p0 = 0.f, p1 = 0.f;
    float* flatOut = out + FLAT_OFF + (size_t)b * 8192;
    const int hh = (tid >> 7) & 1;
    const int pw = tid & 127;
#pragma unroll 4
    for (int c = 0; c < 32; c++) {
        const int o = c * 256 + hh * 128 + pw;
        const float v0 = partf[((2 * hh    ) * 32 + c) * 132 + pw];
        const float v1 = partf[((2 * hh + 1) * 32 + c) * 132 + pw];
        const float f = tanhf(fmaxf(v0, v1));
        flatOut[o] = f;
        p0 = fmaf(f, Wout[2 * o],     p0);
        p1 = fmaf(f, Wout[2 * o + 1], p1);
    }
#pragma unroll
    for (int off = 16; off > 0; off >>= 1) {
        p0 += __shfl_down_sync(0xFFFFFFFFu, p0, off);
        p1 += __shfl_down_sync(0xFFFFFFFFu, p1, off);
    }
    if (lane == 0) { sred[wid] = p0; sred[8 + wid] = p1; }
    __syncthreads();
    if (tid == 0) {
        float s0 = 0.f, s1 = 0.f;
#pragma unroll
        for (int w = 0; w < 8; w++) { s0 += sred[w]; s1 += sred[8 + w]; }
        out[OUT_OFF + 2 * b]     = s0 + bout[0];
        out[OUT_OFF + 2 * b + 1] = s1 + bout[1];
    }
}

// ---------------------------------------------------------------------------
// Launch
// ---------------------------------------------------------------------------
extern "C" void kernel_launch(void* const* d_in, const int* in_sizes, int n_in,
                              void* d_out, int out_size)
{
    const float* r_att   = (const float*)d_in[0];
    const float* p_att   = (const float*)d_in[1];
    const float* r_fun   = (const float*)d_in[2];
    const float* p_fun   = (const float*)d_in[3];
    const int*   idx     = (const int*)  d_in[4];
    const float* W_att1  = (const float*)d_in[5];
    const float* b_att1  = (const float*)d_in[6];
    const float* W_att2  = (const float*)d_in[7];
    const float* b_att2  = (const float*)d_in[8];
    const float* W_fun1  = (const float*)d_in[9];
    const float* b_fun1  = (const float*)d_in[10];
    const float* W_fun2  = (const float*)d_in[11];
    const float* b_fun2  = (const float*)d_in[12];
    const float* conv1_w = (const float*)d_in[13];
    const float* conv1_b = (const float*)d_in[14];
    const float* conv2_w = (const float*)d_in[15];
    const float* conv2_b = (const float*)d_in[16];
    const float* W_out   = (const float*)d_in[17];
    const float* b_out   = (const float*)d_in[18];
    float* out = (float*)d_out;

    void* hid_p = nullptr;
    cudaGetSymbolAddress(&hid_p, g_hid);
    float* hid = (float*)hid_p;

    cudaFuncSetAttribute(mgemm<0>, cudaFuncAttributeMaxDynamicSharedMemorySize, MG_DSMEM);
    cudaFuncSetAttribute(mgemm<1>, cudaFuncAttributeMaxDynamicSharedMemorySize, MG_DSMEM);
    cudaFuncSetAttribute(conv_fused_v2,
                         cudaFuncAttributeMaxDynamicSharedMemorySize, CV_SMEM_BYTES);

    dim3 blk(256);
    const int mtiles = (M_TOT + 127) / 128;   // 28

    mgemm<0><<<dim3(mtiles, N_ATT1 / 128), blk, MG_DSMEM>>>(
        r_att, p_att, N_R, W_att1, b_att1, hid, M_TOT, N_ATT1, K_ATT, N_ATT1, 0);
    mgemm<1><<<dim3(mtiles, N_E / 128), blk, MG_DSMEM>>>(
        hid, hid, M_TOT, W_att2, b_att2, out, M_TOT, N_E, N_ATT1, D_E, 0);

    mgemm<0><<<dim3(mtiles, N_FUN1 / 128), blk, MG_DSMEM>>>(
        r_fun, p_fun, N_R, W_fun1, b_fun1, hid, M_TOT, N_FUN1, K_FUN, N_FUN1, 0);
    mgemm<1><<<dim3(mtiles, N_E / 128), blk, MG_DSMEM>>>(
        hid, hid, M_TOT, W_fun2, b_fun2, out, M_TOT, N_E, N_FUN1, D_E, N_E);

    conv_fused_v2<<<BATCH, blk, CV_SMEM_BYTES>>>(
        out, idx, conv1_w, conv1_b, conv2_w, conv2_b, W_out, b_out, out);
}